// round 2
// baseline (speedup 1.0000x reference)
#include <cuda_runtime.h>
#include <cuda_bf16.h>
#include <math.h>

// ---------------------------------------------------------------------------
// TorchKAN: out = kan(kan(x, w1, a1), w2, a2)
//   kan(X, W, A): S = X @ W^T ; out[b,n] = sum_q A[n,q] * act_q(S[b,n])
// X [B, K] row-major, W [N, K] row-major, A [N, 6]. NT GEMM, both K-contig.
// 128x128x16 tile, 8x8 microtile, 256 thr, 2-stage smem double buffering,
// fused 6-activation epilogue.
// ---------------------------------------------------------------------------

#define BM 128
#define BN 128
#define BK 16
#define TM 8
#define TN 8

// Hidden-layer scratch (B=32768, H=1024). __device__ global: no allocation.
__device__ float g_hidden[32768 * 1024];

__device__ __forceinline__ float act_combine(float s,
                                             float a0, float a1, float a2,
                                             float a3, float a4, float a5) {
    // All six activations from em = exp(-|s|):
    float em  = __expf(-fabsf(s));
    float inv = 1.0f / (1.0f + em);
    float sig = (s >= 0.0f) ? inv : (1.0f - inv);     // sigmoid
    float em2 = em * em;
    float th  = (1.0f - em2) / (1.0f + em2);          // tanh(|s|)
    th        = (s >= 0.0f) ? th : -th;
    float rl  = fmaxf(s, 0.0f);                       // relu
    float lk  = (s > 0.0f) ? s : 0.01f * s;           // leaky_relu(0.01)
    float sp  = rl + __logf(1.0f + em);               // softplus (stable form)
    float el  = (s > 0.0f) ? s : (em - 1.0f);         // elu
    float r;
    r = a0 * sig;
    r = fmaf(a1, th, r);
    r = fmaf(a2, rl, r);
    r = fmaf(a3, lk, r);
    r = fmaf(a4, sp, r);
    r = fmaf(a5, el, r);
    return r;
}

__global__ __launch_bounds__(256, 2)
void kan_gemm_act(const float* __restrict__ Xg,   // [M, K]
                  const float* __restrict__ Wg,   // [N, K]
                  const float* __restrict__ Ag,   // [N, 6]
                  float* __restrict__ Og,         // [M, N]
                  int M, int N, int K)
{
    __shared__ __align__(16) float As[2][BK][BM + 4];
    __shared__ __align__(16) float Bs[2][BK][BN + 4];

    const int tid = threadIdx.x;
    const int bm  = blockIdx.y * BM;
    const int bn  = blockIdx.x * BN;

    const int tx = tid & 15;
    const int ty = tid >> 4;
    const int m0 = ty * TM;
    const int n0 = tx * TN;

    float acc[TM][TN];
#pragma unroll
    for (int i = 0; i < TM; i++)
#pragma unroll
        for (int j = 0; j < TN; j++) acc[i][j] = 0.0f;

    // Loader mapping: each thread loads 2 float4 per tile per operand.
    const int lrow = tid >> 2;        // 0..63
    const int lkq  = (tid & 3) * 4;   // k offset within tile: 0,4,8,12

    const float* Xp = Xg + (size_t)(bm + lrow) * K + lkq;
    const float* Wp = Wg + (size_t)(bn + lrow) * K + lkq;
    const size_t stride64 = (size_t)64 * K;

    const int T = K / BK;

    float4 va0, va1, vb0, vb1;

    // Prologue: tile 0 -> regs -> smem stage 0
    va0 = *(const float4*)(Xp);
    va1 = *(const float4*)(Xp + stride64);
    vb0 = *(const float4*)(Wp);
    vb1 = *(const float4*)(Wp + stride64);
    {
        float* a = &As[0][lkq][0];
        a[0 * (BM + 4) + lrow] = va0.x; a[1 * (BM + 4) + lrow] = va0.y;
        a[2 * (BM + 4) + lrow] = va0.z; a[3 * (BM + 4) + lrow] = va0.w;
        a[0 * (BM + 4) + lrow + 64] = va1.x; a[1 * (BM + 4) + lrow + 64] = va1.y;
        a[2 * (BM + 4) + lrow + 64] = va1.z; a[3 * (BM + 4) + lrow + 64] = va1.w;
        float* b = &Bs[0][lkq][0];
        b[0 * (BN + 4) + lrow] = vb0.x; b[1 * (BN + 4) + lrow] = vb0.y;
        b[2 * (BN + 4) + lrow] = vb0.z; b[3 * (BN + 4) + lrow] = vb0.w;
        b[0 * (BN + 4) + lrow + 64] = vb1.x; b[1 * (BN + 4) + lrow + 64] = vb1.y;
        b[2 * (BN + 4) + lrow + 64] = vb1.z; b[3 * (BN + 4) + lrow + 64] = vb1.w;
    }
    __syncthreads();

    for (int t = 0; t < T; t++) {
        const int s = t & 1;

        // Prefetch next tile into registers (overlaps with compute below).
        if (t + 1 < T) {
            const int k0 = (t + 1) * BK;
            va0 = *(const float4*)(Xp + k0);
            va1 = *(const float4*)(Xp + k0 + stride64);
            vb0 = *(const float4*)(Wp + k0);
            vb1 = *(const float4*)(Wp + k0 + stride64);
        }

        // Compute on stage s.
#pragma unroll
        for (int kk = 0; kk < BK; kk++) {
            float af[TM], bf[TN];
            *(float4*)&af[0] = *(const float4*)&As[s][kk][m0];
            *(float4*)&af[4] = *(const float4*)&As[s][kk][m0 + 4];
            *(float4*)&bf[0] = *(const float4*)&Bs[s][kk][n0];
            *(float4*)&bf[4] = *(const float4*)&Bs[s][kk][n0 + 4];
#pragma unroll
            for (int i = 0; i < TM; i++)
#pragma unroll
                for (int j = 0; j < TN; j++)
                    acc[i][j] = fmaf(af[i], bf[j], acc[i][j]);
        }

        // Store prefetched tile into the other stage, then sync.
        if (t + 1 < T) {
            const int so = s ^ 1;
            float* a = &As[so][lkq][0];
            a[0 * (BM + 4) + lrow] = va0.x; a[1 * (BM + 4) + lrow] = va0.y;
            a[2 * (BM + 4) + lrow] = va0.z; a[3 * (BM + 4) + lrow] = va0.w;
            a[0 * (BM + 4) + lrow + 64] = va1.x; a[1 * (BM + 4) + lrow + 64] = va1.y;
            a[2 * (BM + 4) + lrow + 64] = va1.z; a[3 * (BM + 4) + lrow + 64] = va1.w;
            float* b = &Bs[so][lkq][0];
            b[0 * (BN + 4) + lrow] = vb0.x; b[1 * (BN + 4) + lrow] = vb0.y;
            b[2 * (BN + 4) + lrow] = vb0.z; b[3 * (BN + 4) + lrow] = vb0.w;
            b[0 * (BN + 4) + lrow + 64] = vb1.x; b[1 * (BN + 4) + lrow + 64] = vb1.y;
            b[2 * (BN + 4) + lrow + 64] = vb1.z; b[3 * (BN + 4) + lrow + 64] = vb1.w;
            __syncthreads();
        }
    }

    // Fused activation epilogue.
    float ac[6][TN];
#pragma unroll
    for (int j = 0; j < TN; j++) {
        const float* ap = Ag + (size_t)(bn + n0 + j) * 6;
#pragma unroll
        for (int q = 0; q < 6; q++) ac[q][j] = __ldg(ap + q);
    }

#pragma unroll
    for (int i = 0; i < TM; i++) {
        float4 o0, o1;
        float r[TN];
#pragma unroll
        for (int j = 0; j < TN; j++)
            r[j] = act_combine(acc[i][j], ac[0][j], ac[1][j], ac[2][j],
                               ac[3][j], ac[4][j], ac[5][j]);
        o0.x = r[0]; o0.y = r[1]; o0.z = r[2]; o0.w = r[3];
        o1.x = r[4]; o1.y = r[5]; o1.z = r[6]; o1.w = r[7];
        float* op = Og + (size_t)(bm + m0 + i) * N + bn + n0;
        *(float4*)(op)     = o0;
        *(float4*)(op + 4) = o1;
    }
}

extern "C" void kernel_launch(void* const* d_in, const int* in_sizes, int n_in,
                              void* d_out, int out_size) {
    const float* x  = (const float*)d_in[0];
    const float* w1 = (const float*)d_in[1];
    const float* a1 = (const float*)d_in[2];
    const float* w2 = (const float*)d_in[3];
    const float* a2 = (const float*)d_in[4];
    float* out = (float*)d_out;

    const int D_IN  = 256;
    const int H     = 1024;
    const int D_OUT = 256;
    const int B     = in_sizes[0] / D_IN;   // 32768

    float* hbuf = nullptr;
    cudaGetSymbolAddress((void**)&hbuf, g_hidden);

    dim3 blk(256);
    dim3 g1(H / BN,     B / BM);  // (8, 256)
    dim3 g2(D_OUT / BN, B / BM);  // (2, 256)

    kan_gemm_act<<<g1, blk>>>(x,    w1, a1, hbuf, B, H,     D_IN);
    kan_gemm_act<<<g2, blk>>>(hbuf, w2, a2, out,  B, D_OUT, H);
}

// round 6
// speedup vs baseline: 1.5782x; 1.5782x over previous
#include <cuda_runtime.h>
#include <cuda_fp16.h>
#include <cstdint>
#include <math.h>

// ===========================================================================
// TorchKAN via mma.sync (m16n8k16 fp16, fp32 accum) with fp16x3 split.
//   kan(X, W, A): S = X @ W^T ; out = sum_q A[:,q] * act_q(S)
// fp32 operand = fp16 hi + fp16 lo; S = Ah*Bh + Ah*Bl + Al*Bh (rel ~2^-22).
// Base-sm_100-safe (no tcgen05). Static smem only (36KB), no dynamic smem,
// no cudaFuncSetAttribute, register-direct epilogue.
// ===========================================================================

#define B_SZ    32768
#define DIN_SZ  256
#define H_SZ    1024
#define DOUT_SZ 256

__device__ __half g_xh[B_SZ * DIN_SZ];
__device__ __half g_xl[B_SZ * DIN_SZ];
__device__ __half g_w1h[H_SZ * DIN_SZ];
__device__ __half g_w1l[H_SZ * DIN_SZ];
__device__ __half g_w2h[DOUT_SZ * H_SZ];
__device__ __half g_w2l[DOUT_SZ * H_SZ];
__device__ __half g_hh[(size_t)B_SZ * H_SZ];
__device__ __half g_hl[(size_t)B_SZ * H_SZ];

// ---------------- PTX helpers ----------------------------------------------
__device__ __forceinline__ uint32_t smem_u32(const void* p) {
    uint32_t a;
    asm("{ .reg .u64 t; cvta.to.shared.u64 t, %1; cvt.u32.u64 %0, t; }"
        : "=r"(a) : "l"(p));
    return a;
}

#define LDSM_X4(r, addr)                                                       \
    asm volatile("ldmatrix.sync.aligned.m8n8.x4.shared.b16 {%0,%1,%2,%3}, [%4];" \
                 : "=r"((r)[0]), "=r"((r)[1]), "=r"((r)[2]), "=r"((r)[3])      \
                 : "r"(addr))

#define MMA16816(d, a, b)                                                      \
    asm volatile("mma.sync.aligned.m16n8k16.row.col.f32.f16.f16.f32 "          \
                 "{%0,%1,%2,%3}, {%4,%5,%6,%7}, {%8,%9}, {%0,%1,%2,%3};"       \
                 : "+f"((d)[0]), "+f"((d)[1]), "+f"((d)[2]), "+f"((d)[3])      \
                 : "r"((a)[0]), "r"((a)[1]), "r"((a)[2]), "r"((a)[3]),         \
                   "r"((b)[0]), "r"((b)[1]))

// BK=16 tile: 128 rows x 16 halfs (two 16B chunks/row), 4KB per component.
// phys(row,c) = (row>>2)*128 + ((row&3) + 4*(c ^ ((row>>2)&1)))*16
// Every ldmatrix phase (8 consecutive rows, fixed c) and every STS phase hits
// 8 distinct 16B bank-groups.
__device__ __forceinline__ uint32_t phys(uint32_t row, uint32_t c) {
    return (row >> 2) * 128u + (((row & 3u) + 4u * (c ^ ((row >> 2) & 1u))) << 4);
}

// ---------------- activation -----------------------------------------------
__device__ __forceinline__ float act_combine(float s, float a0, float a1,
                                             float a2, float a3, float a4, float a5) {
    float em  = __expf(-fabsf(s));
    float inv = 1.0f / (1.0f + em);
    float sig = (s >= 0.0f) ? inv : (1.0f - inv);
    float em2 = em * em;
    float th  = (1.0f - em2) / (1.0f + em2);
    th        = (s >= 0.0f) ? th : -th;
    float rl  = fmaxf(s, 0.0f);
    float lk  = (s > 0.0f) ? s : 0.01f * s;
    float sp  = rl + __logf(1.0f + em);
    float el  = (s > 0.0f) ? s : (em - 1.0f);
    float r;
    r = a0 * sig;
    r = fmaf(a1, th, r);
    r = fmaf(a2, rl, r);
    r = fmaf(a3, lk, r);
    r = fmaf(a4, sp, r);
    r = fmaf(a5, el, r);
    return r;
}

// ---------------- split kernel ---------------------------------------------
__global__ __launch_bounds__(256)
void split_kernel(const float4* __restrict__ in,
                  uint2* __restrict__ hi, uint2* __restrict__ lo, int n4) {
    int i = blockIdx.x * 256 + threadIdx.x;
    if (i >= n4) return;
    float4 v = __ldg(in + i);
    union { uint2 u; __half b[4]; } H, L;
    float f[4] = {v.x, v.y, v.z, v.w};
#pragma unroll
    for (int e = 0; e < 4; e++) {
        __half h = __float2half_rn(f[e]);
        H.b[e] = h;
        L.b[e] = __float2half_rn(f[e] - __half2float(h));
    }
    hi[i] = H.u;
    lo[i] = L.u;
}

// ---------------- main GEMM + activation -----------------------------------
// CTA 128x128, BK=16, 8 warps (4 M x 2 N), warp tile 32(M) x 64(N).
#define CSZ  4096          // one component tile bytes
#define STG  16384         // one stage (Ah, Al, Bh, Bl)

template<int OUT_SPLIT>
__global__ __launch_bounds__(256, 1)
void kan_tc(const __half* __restrict__ Ah, const __half* __restrict__ Al,
            const __half* __restrict__ Bh, const __half* __restrict__ Bl,
            const float* __restrict__ Ag,
            float* __restrict__ Of,
            __half* __restrict__ Oh, __half* __restrict__ Ol,
            int Kfull, int Ncols)
{
    __shared__ __align__(16)  float  s_coef[128 * 8];            // 4 KB
    __shared__ __align__(128) __half s_stage[2][4][2048];        // 32 KB

    const int tid  = threadIdx.x;
    const int wid  = tid >> 5;
    const int lane = tid & 31;
    const int wm   = wid >> 1;   // 0..3
    const int wn   = wid & 1;    // 0..1
    const int bm   = blockIdx.y * 128;
    const int bn   = blockIdx.x * 128;

    const uint32_t Sbase = smem_u32(&s_stage[0][0][0]);
    char* Sp = (char*)&s_stage[0][0][0];

    // loader mapping: 1 int4 per component per tile
    const uint32_t lrow = (uint32_t)(tid >> 1);     // 0..127
    const uint32_t lc   = (uint32_t)(tid & 1);      // chunk 0/1
    const uint32_t sw   = phys(lrow, lc);
    const size_t   gA   = (size_t)(bm + lrow) * Kfull + lc * 8;
    const size_t   gB   = (size_t)(bn + lrow) * Kfull + lc * 8;

    // coeffs (pad to 8 floats per col for aligned float4 reads)
    for (int i = tid; i < 128 * 6; i += 256) {
        int c = i / 6, q = i - c * 6;
        s_coef[c * 8 + q] = __ldg(Ag + (size_t)(bn + c) * 6 + q);
    }

    // ldmatrix per-lane byte offsets (within a component tile), precomputed
    const uint32_t rowA0 = (uint32_t)(wm * 32 + ((lane >> 3) & 1) * 8 + (lane & 7));
    const uint32_t cofA  = (uint32_t)(lane >> 4);
    const uint32_t offA0 = phys(rowA0,      cofA);
    const uint32_t offA1 = phys(rowA0 + 16, cofA);
    const uint32_t rowB  = (uint32_t)(wn * 64 + (lane >> 4) * 8 + (lane & 7));
    const uint32_t cofB  = (uint32_t)((lane >> 3) & 1);
    uint32_t offB[4];
#pragma unroll
    for (int p = 0; p < 4; p++) offB[p] = phys(rowB + p * 16, cofB);

    // prologue: tile 0 -> stage 0
    int4 pAh, pAl, pBh, pBl;
    pAh = *(const int4*)(Ah + gA);
    pAl = *(const int4*)(Al + gA);
    pBh = *(const int4*)(Bh + gB);
    pBl = *(const int4*)(Bl + gB);
    *(int4*)(Sp + 0 * CSZ + sw) = pAh;
    *(int4*)(Sp + 1 * CSZ + sw) = pAl;
    *(int4*)(Sp + 2 * CSZ + sw) = pBh;
    *(int4*)(Sp + 3 * CSZ + sw) = pBl;
    __syncthreads();

    float acc[2][8][4];
#pragma unroll
    for (int mi = 0; mi < 2; mi++)
#pragma unroll
        for (int ni = 0; ni < 8; ni++)
#pragma unroll
            for (int e = 0; e < 4; e++) acc[mi][ni][e] = 0.0f;

    const int T = Kfull >> 4;   // BK = 16

    for (int t = 0; t < T; t++) {
        const int s = t & 1;

        if (t + 1 < T) {
            const int k0 = (t + 1) * 16;
            pAh = *(const int4*)(Ah + gA + k0);
            pAl = *(const int4*)(Al + gA + k0);
            pBh = *(const int4*)(Bh + gB + k0);
            pBl = *(const int4*)(Bl + gB + k0);
        }

        const uint32_t stA = Sbase + (uint32_t)s * STG;
        uint32_t ah[2][4], al[2][4], bh[8][2], bl[8][2];
        LDSM_X4(ah[0], stA + 0 * CSZ + offA0);
        LDSM_X4(ah[1], stA + 0 * CSZ + offA1);
        LDSM_X4(al[0], stA + 1 * CSZ + offA0);
        LDSM_X4(al[1], stA + 1 * CSZ + offA1);
#pragma unroll
        for (int p = 0; p < 4; p++) {
            uint32_t tmp[4];
            LDSM_X4(tmp, stA + 2 * CSZ + offB[p]);
            bh[2 * p][0] = tmp[0]; bh[2 * p][1] = tmp[1];
            bh[2 * p + 1][0] = tmp[2]; bh[2 * p + 1][1] = tmp[3];
            LDSM_X4(tmp, stA + 3 * CSZ + offB[p]);
            bl[2 * p][0] = tmp[0]; bl[2 * p][1] = tmp[1];
            bl[2 * p + 1][0] = tmp[2]; bl[2 * p + 1][1] = tmp[3];
        }
#pragma unroll
        for (int mi = 0; mi < 2; mi++)
#pragma unroll
            for (int ni = 0; ni < 8; ni++) {
                MMA16816(acc[mi][ni], ah[mi], bh[ni]);
                MMA16816(acc[mi][ni], ah[mi], bl[ni]);
                MMA16816(acc[mi][ni], al[mi], bh[ni]);
            }

        if (t + 1 < T) {
            char* st = Sp + (s ^ 1) * STG;
            *(int4*)(st + 0 * CSZ + sw) = pAh;
            *(int4*)(st + 1 * CSZ + sw) = pAl;
            *(int4*)(st + 2 * CSZ + sw) = pBh;
            *(int4*)(st + 3 * CSZ + sw) = pBl;
            __syncthreads();
        }
    }

    // ---- register-direct epilogue (no smem staging) ----
    // acc[mi][ni]: d0,d1 -> (rr + mi*16, c..c+1); d2,d3 -> (rr + mi*16 + 8, ...)
    const int rr    = wm * 32 + (lane >> 2);
    const int cbase = wn * 64 + (lane & 3) * 2;

#pragma unroll
    for (int ni = 0; ni < 8; ni++) {
        const int c0 = cbase + ni * 8;
        const float* ap0 = &s_coef[(c0)     * 8];
        const float* ap1 = &s_coef[(c0 + 1) * 8];
        float4 u0 = *(const float4*)ap0; float2 u1 = *(const float2*)(ap0 + 4);
        float4 v0 = *(const float4*)ap1; float2 v1 = *(const float2*)(ap1 + 4);

#pragma unroll
        for (int mi = 0; mi < 2; mi++) {
#pragma unroll
            for (int rh = 0; rh < 2; rh++) {
                const float sa = acc[mi][ni][rh * 2 + 0];
                const float sb = acc[mi][ni][rh * 2 + 1];
                const float ra = act_combine(sa, u0.x, u0.y, u0.z, u0.w, u1.x, u1.y);
                const float rb = act_combine(sb, v0.x, v0.y, v0.z, v0.w, v1.x, v1.y);
                const int row = rr + mi * 16 + rh * 8;
                const size_t o = (size_t)(bm + row) * Ncols + bn + c0;
                if (OUT_SPLIT) {
                    __half ha = __float2half_rn(ra);
                    __half hb = __float2half_rn(rb);
                    __half la = __float2half_rn(ra - __half2float(ha));
                    __half lb = __float2half_rn(rb - __half2float(hb));
                    *(__half2*)(Oh + o) = __halves2half2(ha, hb);
                    *(__half2*)(Ol + o) = __halves2half2(la, lb);
                } else {
                    *(float2*)(Of + o) = make_float2(ra, rb);
                }
            }
        }
    }
}

// ---------------- host launcher --------------------------------------------
extern "C" void kernel_launch(void* const* d_in, const int* in_sizes, int n_in,
                              void* d_out, int out_size) {
    const float* x  = (const float*)d_in[0];
    const float* w1 = (const float*)d_in[1];
    const float* a1 = (const float*)d_in[2];
    const float* w2 = (const float*)d_in[3];
    const float* a2 = (const float*)d_in[4];
    float* out = (float*)d_out;

    __half *xh, *xl, *w1h, *w1l, *w2h, *w2l, *hh, *hl;
    cudaGetSymbolAddress((void**)&xh,  g_xh);
    cudaGetSymbolAddress((void**)&xl,  g_xl);
    cudaGetSymbolAddress((void**)&w1h, g_w1h);
    cudaGetSymbolAddress((void**)&w1l, g_w1l);
    cudaGetSymbolAddress((void**)&w2h, g_w2h);
    cudaGetSymbolAddress((void**)&w2l, g_w2l);
    cudaGetSymbolAddress((void**)&hh,  g_hh);
    cudaGetSymbolAddress((void**)&hl,  g_hl);

    const int nx4 = (B_SZ * DIN_SZ) / 4;
    const int nw4 = (H_SZ * DIN_SZ) / 4;
    split_kernel<<<nx4 / 256, 256>>>((const float4*)x,  (uint2*)xh,  (uint2*)xl,  nx4);
    split_kernel<<<nw4 / 256, 256>>>((const float4*)w1, (uint2*)w1h, (uint2*)w1l, nw4);
    split_kernel<<<nw4 / 256, 256>>>((const float4*)w2, (uint2*)w2h, (uint2*)w2l, nw4);

    // layer 1: [32768,256] x [1024,256]^T -> hidden fp16 hi/lo
    kan_tc<1><<<dim3(H_SZ / 128, B_SZ / 128), 256>>>(
        xh, xl, w1h, w1l, a1, nullptr, hh, hl, DIN_SZ, H_SZ);

    // layer 2: [32768,1024] x [256,1024]^T -> out fp32
    kan_tc<0><<<dim3(DOUT_SZ / 128, B_SZ / 128), 256>>>(
        hh, hl, w2h, w2l, a2, out, nullptr, nullptr, H_SZ, DOUT_SZ);
}